// round 2
// baseline (speedup 1.0000x reference)
#include <cuda_runtime.h>

// Problem constants (fixed shapes)
#define BB 16
#define KK 64
#define HH 96
#define WW 96
#define PLANE   (HH * WW)      // 9216
#define NPLANES (BB * KK)      // 1024
#define VECS    (PLANE / 4)    // 2304 float4 per plane
#define WVEC    (WW / 4)       // 24 float4 per row

// Output layout (flat float32)
#define DK_ELEMS   (NPLANES * PLANE)          // 9437184
#define KP_ELEMS   (BB * 3 * KK * 2)          // 6144
#define KP_OFF     (2 * DK_ELEMS)             // 18874368
#define ZETA_OFF   (KP_OFF + 2 * KP_ELEMS)    // 18886656

// Scratch for per-plane weighted sums (allocation-free: __device__ globals)
__device__ float g_kx[2 * NPLANES];
__device__ float g_ky[2 * NPLANES];

__device__ __forceinline__ float sigmoidf_(float x) {
    return 1.0f / (1.0f + expf(-x));
}

// Kernel 1: one CTA per (stream, b, k) plane.
// Streams sigmoid(plane) to output while reducing sum, sum*x, sum*y.
__global__ __launch_bounds__(256) void sigmoid_reduce_kernel(
    const float* __restrict__ Rk,
    const float* __restrict__ tfRk,
    float* __restrict__ out)
{
    const int bid = blockIdx.x;        // 0..2047
    const int s   = bid >> 10;         // stream: 0 = Rk, 1 = tf_Rk
    const int p   = bid & 1023;        // plane index (b*K + k)

    const float4* __restrict__ in4 =
        (const float4*)((s ? tfRk : Rk) + (size_t)p * PLANE);
    float4* __restrict__ out4 =
        (float4*)(out + (size_t)s * DK_ELEMS + (size_t)p * PLANE);

    float sum = 0.f, sx = 0.f, sy = 0.f;

    #pragma unroll 3
    for (int v = threadIdx.x; v < VECS; v += 256) {
        float4 r = in4[v];
        float4 d;
        d.x = sigmoidf_(r.x);
        d.y = sigmoidf_(r.y);
        d.z = sigmoidf_(r.z);
        d.w = sigmoidf_(r.w);
        out4[v] = d;

        const int row = v / WVEC;
        const int c0  = (v - row * WVEC) * 4;
        const float e = d.x + d.y + d.z + d.w;
        sum += e;
        sy  += (float)row * e;
        sx  += (float)c0 * e + (d.y + 2.0f * d.z + 3.0f * d.w);
    }

    // Warp reduce
    #pragma unroll
    for (int o = 16; o > 0; o >>= 1) {
        sum += __shfl_down_sync(0xFFFFFFFFu, sum, o);
        sx  += __shfl_down_sync(0xFFFFFFFFu, sx,  o);
        sy  += __shfl_down_sync(0xFFFFFFFFu, sy,  o);
    }

    __shared__ float sm[3][8];
    const int lane = threadIdx.x & 31;
    const int warp = threadIdx.x >> 5;
    if (lane == 0) { sm[0][warp] = sum; sm[1][warp] = sx; sm[2][warp] = sy; }
    __syncthreads();

    if (threadIdx.x == 0) {
        float S = 0.f, X = 0.f, Y = 0.f;
        #pragma unroll
        for (int i = 0; i < 8; i++) { S += sm[0][i]; X += sm[1][i]; Y += sm[2][i]; }
        out[ZETA_OFF + bid] = S;   // zeta region: [get_zeta(1024) | tf_get_zeta(1024)] = bid order
        g_kx[bid] = X;
        g_ky[bid] = Y;
    }
}

// Kernel 2: soft-argmax decode for all 2048 (stream, b, k) items.
__global__ __launch_bounds__(256) void decode_kernel(float* __restrict__ out)
{
    const int t = blockIdx.x * blockDim.x + threadIdx.x;
    if (t >= 2 * NPLANES) return;
    const int s = t >> 10;
    const int p = t & 1023;

    const float zeta = out[ZETA_OFF + t];
    const float x = rintf(g_kx[t] / zeta);   // RNE == jnp.round
    const float y = rintf(g_ky[t] / zeta);

    // Gather d = Dk[b,k,y,x] from the already-written sigmoid output
    const float* __restrict__ D = out + (size_t)s * DK_ELEMS + (size_t)p * PLANE;
    const float d = D[(int)y * WW + (int)x];

    const int b = p / KK;
    const int k = p - b * KK;
    float* __restrict__ kp = out + KP_OFF + (size_t)s * KP_ELEMS + (size_t)b * (3 * KK * 2);

    kp[k * 2 + 0] = x;
    kp[k * 2 + 1] = y;
    kp[(KK + k) * 2 + 0]     = truncf(x + x * d);
    kp[(KK + k) * 2 + 1]     = truncf(y + y * d);
    kp[(2 * KK + k) * 2 + 0] = truncf(x - x * d);
    kp[(2 * KK + k) * 2 + 1] = truncf(y - y * d);
}

extern "C" void kernel_launch(void* const* d_in, const int* in_sizes, int n_in,
                              void* d_out, int out_size)
{
    const float* Rk   = (const float*)d_in[0];
    const float* tfRk = (const float*)d_in[1];
    // d_in[2], d_in[3] are my_height / my_width scalars; shapes are fixed (96x96).
    float* out = (float*)d_out;

    sigmoid_reduce_kernel<<<2 * NPLANES, 256>>>(Rk, tfRk, out);
    decode_kernel<<<(2 * NPLANES + 255) / 256, 256>>>(out);
}

// round 4
// speedup vs baseline: 1.4474x; 1.4474x over previous
#include <cuda_runtime.h>

// Problem constants (fixed shapes)
#define BB 16
#define KK 64
#define HH 96
#define WW 96
#define PLANE   (HH * WW)      // 9216
#define NPLANES (BB * KK)      // 1024
#define VECS    (PLANE / 4)    // 2304 float4 per plane
#define WVEC    (WW / 4)       // 24 float4 per row
#define ITERS   (VECS / 256)   // 9 float4 per thread, exact

// Output layout (flat float32)
#define DK_ELEMS   (NPLANES * PLANE)          // 9437184
#define KP_ELEMS   (BB * 3 * KK * 2)          // 6144
#define KP_OFF     (2 * DK_ELEMS)             // 18874368
#define ZETA_OFF   (KP_OFF + 2 * KP_ELEMS)    // 18886656

__device__ __forceinline__ float sigmoidf_(float x) {
    // __expf keeps the dependency chain short (mul + MUFU.EX2 + MUFU.RCP).
    // Used identically in the stream loop and the decode gather so the
    // recomputed d matches the stored Dk value bitwise.
    return 1.0f / (1.0f + __expf(-x));
}

// One CTA per (stream, b, k) plane: streams sigmoid(plane) to out while
// reducing sum / sum*x / sum*y, then thread 0 performs the soft-argmax
// decode for this plane. Single kernel, single launch.
__global__ __launch_bounds__(256) void fused_kernel(
    const float* __restrict__ Rk,
    const float* __restrict__ tfRk,
    float* __restrict__ out)
{
    const int bid = blockIdx.x;        // 0..2047
    const int s   = bid >> 10;         // stream: 0 = Rk, 1 = tf_Rk
    const int p   = bid & 1023;        // plane index (b*K + k)

    const float* __restrict__ in_plane = (s ? tfRk : Rk) + (size_t)p * PLANE;
    const float4* __restrict__ in4  = (const float4*)in_plane;
    float4* __restrict__ out4 =
        (float4*)(out + (size_t)s * DK_ELEMS + (size_t)p * PLANE);

    // Batch all 9 loads up front: MLP=9 per thread, latency fully overlapped.
    float4 r[ITERS];
    #pragma unroll
    for (int i = 0; i < ITERS; i++)
        r[i] = in4[threadIdx.x + i * 256];

    float sum = 0.f, sx = 0.f, sy = 0.f;

    #pragma unroll
    for (int i = 0; i < ITERS; i++) {
        const int v = threadIdx.x + i * 256;
        float4 d;
        d.x = sigmoidf_(r[i].x);
        d.y = sigmoidf_(r[i].y);
        d.z = sigmoidf_(r[i].z);
        d.w = sigmoidf_(r[i].w);
        out4[v] = d;

        const int row = v / WVEC;
        const int c0  = (v - row * WVEC) * 4;
        const float e = d.x + d.y + d.z + d.w;
        sum += e;
        sy  += (float)row * e;
        sx  += (float)c0 * e + (d.y + 2.0f * d.z + 3.0f * d.w);
    }

    // Warp reduce
    #pragma unroll
    for (int o = 16; o > 0; o >>= 1) {
        sum += __shfl_down_sync(0xFFFFFFFFu, sum, o);
        sx  += __shfl_down_sync(0xFFFFFFFFu, sx,  o);
        sy  += __shfl_down_sync(0xFFFFFFFFu, sy,  o);
    }

    __shared__ float sm[3][8];
    const int lane = threadIdx.x & 31;
    const int warp = threadIdx.x >> 5;
    if (lane == 0) { sm[0][warp] = sum; sm[1][warp] = sx; sm[2][warp] = sy; }
    __syncthreads();

    if (threadIdx.x == 0) {
        float S = 0.f, X = 0.f, Y = 0.f;
        #pragma unroll
        for (int i = 0; i < 8; i++) { S += sm[0][i]; X += sm[1][i]; Y += sm[2][i]; }

        // zeta region: [get_zeta(1024) | tf_get_zeta(1024)] == bid order
        out[ZETA_OFF + bid] = S;

        // Soft-argmax decode for this plane (thread 0 only).
        const float x = rintf(X / S);   // RNE == jnp.round
        const float y = rintf(Y / S);

        // d = Dk[b,k,y,x]: recompute from the read-only input — bitwise
        // identical to the value this CTA streamed to out.
        const float d = sigmoidf_(in_plane[(int)y * WW + (int)x]);

        const int b = p / KK;
        const int k = p - b * KK;
        float* __restrict__ kp =
            out + KP_OFF + (size_t)s * KP_ELEMS + (size_t)b * (3 * KK * 2);

        kp[k * 2 + 0] = x;
        kp[k * 2 + 1] = y;
        kp[(KK + k) * 2 + 0]     = truncf(x + x * d);
        kp[(KK + k) * 2 + 1]     = truncf(y + y * d);
        kp[(2 * KK + k) * 2 + 0] = truncf(x - x * d);
        kp[(2 * KK + k) * 2 + 1] = truncf(y - y * d);
    }
}

extern "C" void kernel_launch(void* const* d_in, const int* in_sizes, int n_in,
                              void* d_out, int out_size)
{
    const float* Rk   = (const float*)d_in[0];
    const float* tfRk = (const float*)d_in[1];
    // d_in[2], d_in[3] are my_height / my_width scalars; shapes fixed (96x96).
    float* out = (float*)d_out;

    fused_kernel<<<2 * NPLANES, 256>>>(Rk, tfRk, out);
}